// round 1
// baseline (speedup 1.0000x reference)
#include <cuda_runtime.h>
#include <math.h>

// ---------------- problem constants ----------------
#define BB   8
#define TT   2048
#define CC   512
#define HH   16
#define HSZ  32
#define BT   (BB*TT)            // 16384
#define BTC  (BT*CC)            // 8388608

// ---------------- scratch (static device memory; no allocs) ----------------
__device__ float g_xx [BTC];
__device__ float g_xxx[BTC];
__device__ float g_mixpre[BT*160];
__device__ float g_x5 [5*(size_t)BTC];   // xw xk xv xr xg
__device__ float g_r  [BTC];
__device__ float g_k  [BTC];
__device__ float g_v  [BTC];
__device__ float g_g  [BTC];
__device__ float g_wt [BT*64];
__device__ float g_dec[BTC];
__device__ float g_y  [BTC];             // layout (b,h,t,i)
__device__ float g_yg [BTC];             // (b,t,c) gated+normed

// ---------------- prep: xx = shift(x)-x ; xxx = x + xx*time_maa_x ----------------
__global__ void prep_kernel(const float* __restrict__ x,
                            const float* __restrict__ tmx,
                            float* __restrict__ xx,
                            float* __restrict__ xxx)
{
    int i4 = blockIdx.x * blockDim.x + threadIdx.x;
    if (i4 >= BTC/4) return;
    size_t idx = (size_t)i4 * 4;
    int m = (int)(idx / CC);
    int c = (int)(idx % CC);
    int t = m % TT;
    float4 xv = *(const float4*)(x + idx);
    float4 xs;
    if (t == 0) { xs.x = xs.y = xs.z = xs.w = 0.f; }
    else        { xs = *(const float4*)(x + idx - CC); }
    float4 tm = *(const float4*)(tmx + c);
    float4 d, e;
    d.x = xs.x - xv.x; d.y = xs.y - xv.y; d.z = xs.z - xv.z; d.w = xs.w - xv.w;
    e.x = fmaf(d.x, tm.x, xv.x); e.y = fmaf(d.y, tm.y, xv.y);
    e.z = fmaf(d.z, tm.z, xv.z); e.w = fmaf(d.w, tm.w, xv.w);
    *(float4*)(xx  + idx) = d;
    *(float4*)(xxx + idx) = e;
}

// ---------------- generic fp32 GEMM:  C[m,n] = epi( sum_k A[m,k]*B'[k,n] ) ----------------
// BNN=0: B is (N x K) row-major (use row n, i.e. y = A @ B^T)   -> no N guards needed (N=512 use only)
// BNN=1: B is (K x N) row-major                                  -> N guarded
enum { EPI_NONE=0, EPI_TANH=1, EPI_SILU=2, EPI_MIX=3, EPI_DECAY=4 };

template<int EPI>
__device__ __forceinline__ float apply_epi(float v, int col, size_t rx,
                                           const float* __restrict__ vecn,
                                           const float* __restrict__ ex,
                                           const float* __restrict__ exx)
{
    if constexpr (EPI == EPI_TANH)  { return tanhf(v); }
    if constexpr (EPI == EPI_SILU)  { return v / (1.f + expf(-v)); }
    if constexpr (EPI == EPI_MIX)   { return fmaf(exx[rx+col], vecn[col] + v, ex[rx+col]); }
    if constexpr (EPI == EPI_DECAY) { return expf(-expf(vecn[col] + v)); }
    return v;
}

template<int BNN, int EPI>
__global__ void __launch_bounds__(256, 2)
gemm_f32(const float* __restrict__ A, int lda,
         const float* __restrict__ Bm, int ldb,
         float* __restrict__ Cm, int ldc,
         int N, int K,
         const float* __restrict__ vecn,
         const float* __restrict__ ex,
         const float* __restrict__ exx)
{
    __shared__ float As[8][132];
    __shared__ float Bs[8][132];
    const int tid = threadIdx.x;
    const int m0 = blockIdx.y * 128;
    const int n0 = blockIdx.x * 128;

    const int lrow = tid >> 1;          // 0..127
    const int lk   = (tid & 1) * 4;     // 0 or 4
    const float* Ap = A + (size_t)(m0 + lrow) * lda + lk;

    const int bnrow  = tid >> 5;        // 0..7 (NN)
    const int bncol4 = (tid & 31) * 4;  // 0..124 (NN)
    const float* Bp;
    if constexpr (BNN) Bp = Bm + (size_t)bnrow * ldb + (n0 + bncol4);
    else               Bp = Bm + (size_t)(n0 + lrow) * ldb + lk;

    float4 ar = *(const float4*)Ap;
    float4 br;
    if constexpr (!BNN) {
        br = *(const float4*)Bp;
    } else {
        int col = n0 + bncol4;
        if (col + 3 < N) br = *(const float4*)Bp;
        else {
            br.x = (col     < N) ? Bp[0] : 0.f;
            br.y = (col + 1 < N) ? Bp[1] : 0.f;
            br.z = (col + 2 < N) ? Bp[2] : 0.f;
            br.w = (col + 3 < N) ? Bp[3] : 0.f;
        }
    }

    float acc[8][8];
    #pragma unroll
    for (int i = 0; i < 8; ++i)
        #pragma unroll
        for (int j = 0; j < 8; ++j) acc[i][j] = 0.f;

    const int tx = tid & 15, ty = tid >> 4;
    const int KT = K >> 3;

    for (int kt = 0; kt < KT; ++kt) {
        As[lk+0][lrow] = ar.x; As[lk+1][lrow] = ar.y;
        As[lk+2][lrow] = ar.z; As[lk+3][lrow] = ar.w;
        if constexpr (!BNN) {
            Bs[lk+0][lrow] = br.x; Bs[lk+1][lrow] = br.y;
            Bs[lk+2][lrow] = br.z; Bs[lk+3][lrow] = br.w;
        } else {
            *(float4*)&Bs[bnrow][bncol4] = br;
        }
        __syncthreads();

        if (kt + 1 < KT) {
            ar = *(const float4*)(Ap + (kt + 1) * 8);
            if constexpr (!BNN) {
                br = *(const float4*)(Bp + (kt + 1) * 8);
            } else {
                const float* bp2 = Bp + (size_t)(kt + 1) * 8 * ldb;
                int col = n0 + bncol4;
                if (col + 3 < N) br = *(const float4*)bp2;
                else {
                    br.x = (col     < N) ? bp2[0] : 0.f;
                    br.y = (col + 1 < N) ? bp2[1] : 0.f;
                    br.z = (col + 2 < N) ? bp2[2] : 0.f;
                    br.w = (col + 3 < N) ? bp2[3] : 0.f;
                }
            }
        }

        #pragma unroll
        for (int kk = 0; kk < 8; ++kk) {
            float a[8], bb[8];
            *(float4*)&a[0]  = *(const float4*)&As[kk][ty*8];
            *(float4*)&a[4]  = *(const float4*)&As[kk][ty*8+4];
            *(float4*)&bb[0] = *(const float4*)&Bs[kk][tx*8];
            *(float4*)&bb[4] = *(const float4*)&Bs[kk][tx*8+4];
            #pragma unroll
            for (int i = 0; i < 8; ++i)
                #pragma unroll
                for (int j = 0; j < 8; ++j)
                    acc[i][j] = fmaf(a[i], bb[j], acc[i][j]);
        }
        __syncthreads();
    }

    #pragma unroll
    for (int i = 0; i < 8; ++i) {
        int row = m0 + ty * 8 + i;
        size_t rb = (size_t)row * ldc;
        size_t rx = (size_t)row * CC;
        #pragma unroll
        for (int j = 0; j < 8; j += 4) {
            int col = n0 + tx * 8 + j;
            if (col < N) {
                float4 o;
                o.x = apply_epi<EPI>(acc[i][j+0], col+0, rx, vecn, ex, exx);
                o.y = apply_epi<EPI>(acc[i][j+1], col+1, rx, vecn, ex, exx);
                o.z = apply_epi<EPI>(acc[i][j+2], col+2, rx, vecn, ex, exx);
                o.w = apply_epi<EPI>(acc[i][j+3], col+3, rx, vecn, ex, exx);
                *(float4*)&Cm[rb + col] = o;
            }
        }
    }
}

// ---------------- WKV6 scan ----------------
// Block = one (b,h). warp = value index i, lane = key index j.
// S[j,i] one register/thread. y_t[i] = sum_j r_j*(S + u_j*k_j*v_i); S = d_j*S + k_j*v_i.
__global__ void __launch_bounds__(1024)
wkv_scan(const float* __restrict__ r, const float* __restrict__ k,
         const float* __restrict__ v, const float* __restrict__ d,
         const float* __restrict__ u, float* __restrict__ y)
{
    int bh = blockIdx.x;
    int b = bh >> 4, h = bh & 15;
    int warp = threadIdx.x >> 5, lane = threadIdx.x & 31;
    size_t base = ((size_t)b * TT) * CC + h * HSZ;

    const float* rp = r + base + lane;
    const float* kp = k + base + lane;
    const float* dp = d + base + lane;
    const float* vp = v + base + warp;
    float* yp = y + ((size_t)bh * TT) * HSZ + warp;

    float uj = u[h * HSZ + lane];
    float S = 0.f;
    float rc = *rp, kc = *kp, dc = *dp, vc = *vp;

    for (int t = 0; t < TT; ++t) {
        float rn = 0.f, kn = 0.f, dn = 0.f, vn = 0.f;
        if (t + 1 < TT) {
            size_t off = (size_t)(t + 1) * CC;
            rn = rp[off]; kn = kp[off]; dn = dp[off]; vn = vp[off];
        }
        float kv  = kc * vc;
        float tmp = rc * fmaf(uj, kv, S);
        tmp += __shfl_xor_sync(0xffffffffu, tmp, 16);
        tmp += __shfl_xor_sync(0xffffffffu, tmp, 8);
        tmp += __shfl_xor_sync(0xffffffffu, tmp, 4);
        tmp += __shfl_xor_sync(0xffffffffu, tmp, 2);
        tmp += __shfl_xor_sync(0xffffffffu, tmp, 1);
        S = fmaf(dc, S, kv);
        if (lane == 0) yp[(size_t)t * HSZ] = tmp;
        rc = rn; kc = kn; dc = dn; vc = vn;
    }
}

// ---------------- per-head groupnorm + gate ----------------
// one warp per (b,h,t). y layout (b,h,t,i) -> out (b,t,c) = ((y-mu)*rstd*lnw+lnb)*g
__global__ void __launch_bounds__(256)
gn_gate(const float* __restrict__ y, const float* __restrict__ g,
        const float* __restrict__ lnw, const float* __restrict__ lnb,
        float* __restrict__ out)
{
    int gwid = blockIdx.x * (blockDim.x >> 5) + (threadIdx.x >> 5);
    int lane = threadIdx.x & 31;
    if (gwid >= BB * HH * TT) return;
    int bh = gwid / TT;
    int t  = gwid % TT;
    int b = bh >> 4, h = bh & 15;

    float yv = y[(size_t)gwid * HSZ + lane];
    float s = yv, s2 = yv * yv;
    #pragma unroll
    for (int off = 16; off >= 1; off >>= 1) {
        s  += __shfl_xor_sync(0xffffffffu, s,  off);
        s2 += __shfl_xor_sync(0xffffffffu, s2, off);
    }
    float mu  = s * (1.f / HSZ);
    float var = s2 * (1.f / HSZ) - mu * mu;
    float rstd = rsqrtf(var + 1e-5f);
    int cidx = h * HSZ + lane;
    float yn = fmaf((yv - mu) * rstd, lnw[cidx], lnb[cidx]);
    size_t oidx = ((size_t)b * TT + t) * CC + cidx;
    out[oidx] = yn * g[oidx];
}

// ---------------- host launcher ----------------
extern "C" void kernel_launch(void* const* d_in, const int* in_sizes, int n_in,
                              void* d_out, int out_size)
{
    const float* x     = (const float*)d_in[0];
    const float* tmxv  = (const float*)d_in[1];
    const float* tm5[5] = { (const float*)d_in[2], (const float*)d_in[3],
                            (const float*)d_in[4], (const float*)d_in[5],
                            (const float*)d_in[6] };               // w,k,v,r,g
    const float* w1    = (const float*)d_in[7];    // (C,160)
    const float* w2    = (const float*)d_in[8];    // (5,32,C)
    const float* tdec  = (const float*)d_in[9];    // (C)
    const float* tdw1  = (const float*)d_in[10];   // (C,64)
    const float* tdw2  = (const float*)d_in[11];   // (64,C)
    const float* faaaa = (const float*)d_in[12];   // (H,HS)
    const float* Wr    = (const float*)d_in[13];
    const float* Wk    = (const float*)d_in[14];
    const float* Wv    = (const float*)d_in[15];
    const float* Wg    = (const float*)d_in[16];
    const float* Wo    = (const float*)d_in[17];
    const float* lnw   = (const float*)d_in[18];
    const float* lnb   = (const float*)d_in[19];
    float* out = (float*)d_out;

    float *p_xx, *p_xxx, *p_mix, *p_x5, *p_r, *p_k, *p_v, *p_g, *p_wt, *p_dec, *p_y, *p_yg;
    cudaGetSymbolAddress((void**)&p_xx,  g_xx);
    cudaGetSymbolAddress((void**)&p_xxx, g_xxx);
    cudaGetSymbolAddress((void**)&p_mix, g_mixpre);
    cudaGetSymbolAddress((void**)&p_x5,  g_x5);
    cudaGetSymbolAddress((void**)&p_r,   g_r);
    cudaGetSymbolAddress((void**)&p_k,   g_k);
    cudaGetSymbolAddress((void**)&p_v,   g_v);
    cudaGetSymbolAddress((void**)&p_g,   g_g);
    cudaGetSymbolAddress((void**)&p_wt,  g_wt);
    cudaGetSymbolAddress((void**)&p_dec, g_dec);
    cudaGetSymbolAddress((void**)&p_y,   g_y);
    cudaGetSymbolAddress((void**)&p_yg,  g_yg);

    // 1) token shift + xxx
    prep_kernel<<<(BTC/4 + 255)/256, 256>>>(x, tmxv, p_xx, p_xxx);

    dim3 g160(2, BT/128), g512(4, BT/128), g64(1, BT/128);

    // 2) mixpre = tanh(xxx @ w1)   (NN: K=512, N=160)
    gemm_f32<1, EPI_TANH><<<g160, 256>>>(p_xxx, CC, w1, 160, p_mix, 160,
                                         160, 512, nullptr, nullptr, nullptr);

    // 3) xf = x + xx*(tmaa_f + mixpre_f @ w2_f)   (NN: K=32, N=512) x5
    for (int f = 0; f < 5; ++f) {
        gemm_f32<1, EPI_MIX><<<g512, 256>>>(p_mix + f*32, 160,
                                            w2 + (size_t)f*32*CC, CC,
                                            p_x5 + (size_t)f*BTC, CC,
                                            512, 32, tm5[f], x, p_xx);
    }

    // 4) projections (NT: y = X @ W^T), K=N=512
    gemm_f32<0, EPI_NONE><<<g512, 256>>>(p_x5 + 3*(size_t)BTC, CC, Wr, CC, p_r, CC,
                                         512, 512, nullptr, nullptr, nullptr);
    gemm_f32<0, EPI_NONE><<<g512, 256>>>(p_x5 + 1*(size_t)BTC, CC, Wk, CC, p_k, CC,
                                         512, 512, nullptr, nullptr, nullptr);
    gemm_f32<0, EPI_NONE><<<g512, 256>>>(p_x5 + 2*(size_t)BTC, CC, Wv, CC, p_v, CC,
                                         512, 512, nullptr, nullptr, nullptr);
    gemm_f32<0, EPI_SILU><<<g512, 256>>>(p_x5 + 4*(size_t)BTC, CC, Wg, CC, p_g, CC,
                                         512, 512, nullptr, nullptr, nullptr);

    // 5) decay: wt = tanh(xw @ tdw1); dec = exp(-exp(tdec + wt @ tdw2))
    gemm_f32<1, EPI_TANH><<<g64, 256>>>(p_x5 + 0, CC, tdw1, 64, p_wt, 64,
                                        64, 512, nullptr, nullptr, nullptr);
    gemm_f32<1, EPI_DECAY><<<g512, 256>>>(p_wt, 64, tdw2, CC, p_dec, CC,
                                          512, 64, tdec, nullptr, nullptr);

    // 6) WKV6 scan
    wkv_scan<<<BB*HH, 1024>>>(p_r, p_k, p_v, p_dec, faaaa, p_y);

    // 7) groupnorm + gate
    gn_gate<<<(BB*HH*TT)/8, 256>>>(p_y, p_g, lnw, lnb, p_yg);

    // 8) out = yg @ Wo^T
    gemm_f32<0, EPI_NONE><<<g512, 256>>>(p_yg, CC, Wo, CC, out, CC,
                                         512, 512, nullptr, nullptr, nullptr);
}

// round 3
// speedup vs baseline: 1.3803x; 1.3803x over previous
#include <cuda_runtime.h>
#include <cuda_bf16.h>
#include <math.h>
#include <stdint.h>

// ---------------- problem constants ----------------
#define BB   8
#define TT   2048
#define CC   512
#define HH   16
#define HSZ  32
#define BT   (BB*TT)            // 16384
#define BTC  8388608            // BT*CC

// ---------------- scratch (static device memory; no allocs) ----------------
__device__ float g_xx [BTC];
__device__ float g_xxx[BTC];
__device__ float g_mixpre[BT*160];
__device__ float g_x5 [5*(size_t)BTC];   // xw xk xv xr xg
__device__ float g_r  [BTC];
__device__ float g_k  [BTC];
__device__ float g_v  [BTC];
__device__ float g_g  [BTC];
__device__ float g_wt [BT*64];
__device__ float g_dec[BTC];
__device__ float g_y  [BTC];             // layout (b,h,t,i)
__device__ float g_yg [BTC];             // (b,t,c) gated+normed

// ---------------- small helpers ----------------
__device__ __forceinline__ uint32_t smem_u32(const void* p) {
    uint32_t a;
    asm("{ .reg .u64 t; cvta.to.shared.u64 t, %1; cvt.u32.u64 %0, t; }" : "=r"(a) : "l"(p));
    return a;
}

__device__ __forceinline__ void ldsm4(uint32_t* r, uint32_t addr) {
    asm volatile("ldmatrix.sync.aligned.m8n8.x4.shared.b16 {%0,%1,%2,%3}, [%4];"
                 : "=r"(r[0]), "=r"(r[1]), "=r"(r[2]), "=r"(r[3]) : "r"(addr));
}

__device__ __forceinline__ void mma16816(float* c, const uint32_t* a, const uint32_t* b) {
    asm volatile("mma.sync.aligned.m16n8k16.row.col.f32.bf16.bf16.f32 "
                 "{%0,%1,%2,%3}, {%4,%5,%6,%7}, {%8,%9}, {%0,%1,%2,%3};"
                 : "+f"(c[0]), "+f"(c[1]), "+f"(c[2]), "+f"(c[3])
                 : "r"(a[0]), "r"(a[1]), "r"(a[2]), "r"(a[3]),
                   "r"(b[0]), "r"(b[1]));
}

// split fp32 pair into bf16 hi pair + bf16 lo (residual) pair
__device__ __forceinline__ void split2(float f0, float f1, uint32_t& hi, uint32_t& lo) {
    __nv_bfloat162 h = __floats2bfloat162_rn(f0, f1);
    float r0 = f0 - __bfloat162float(h.x);
    float r1 = f1 - __bfloat162float(h.y);
    __nv_bfloat162 l = __floats2bfloat162_rn(r0, r1);
    hi = *(uint32_t*)&h;
    lo = *(uint32_t*)&l;
}

// ---------------- epilogues ----------------
enum { EPI_NONE=0, EPI_TANH=1, EPI_SILU=2, EPI_MIX=3, EPI_DECAY=4 };

template<int EPI>
__device__ __forceinline__ float apply_epi(float v, int col, size_t rx,
                                           const float* __restrict__ vecn,
                                           const float* __restrict__ ex,
                                           const float* __restrict__ exx)
{
    if constexpr (EPI == EPI_TANH)  { return tanhf(v); }
    if constexpr (EPI == EPI_SILU)  { return v / (1.f + expf(-v)); }
    if constexpr (EPI == EPI_MIX)   { return fmaf(exx[rx+col], vecn[col] + v, ex[rx+col]); }
    if constexpr (EPI == EPI_DECAY) { return expf(-expf(vecn[col] + v)); }
    return v;
}

// ================= mma.sync bf16 split GEMM =================
// C[m,n] = epi( sum_k A[m,k] * B'[k,n] )
// BTRANS=0: B is (N,K) row-major (projection weights; N==512, no guards)
// BTRANS=1: B is (K,N) row-major -> transpose on load, N-guarded
// 3 passes: D += Ahi*Bhi + Alo*Bhi + Ahi*Blo (fp32-like accuracy)
// CTA tile 128x128x32; 8 warps (2x4); warp tile 64x32; smem double buffered.
// K is always a multiple of 32 here (512, 64, 32).
#define PADS 40                                  // bf16 elems per smem row
#define MAT_BYTES (128*PADS*2)                   // 10240
#define STG_BYTES (4*MAT_BYTES)                  // 40960 (Ahi,Alo,Bhi,Blo)
#define DSMEM_BYTES (2*STG_BYTES)                // 81920

template<int BTRANS, int EPI>
__global__ void __launch_bounds__(256)
mgemm(const float* __restrict__ A, int lda,
      const float* __restrict__ B, int ldb,
      float* __restrict__ C, int ldc,
      int N, int K,
      const float* __restrict__ vecn,
      const float* __restrict__ ex,
      const float* __restrict__ exx)
{
    extern __shared__ __align__(16) char sm[];
    const int tid  = threadIdx.x;
    const int warp = tid >> 5;
    const int lane = tid & 31;
    const int m0 = blockIdx.y * 128;
    const int n0 = blockIdx.x * 128;
    const int wm = (warp >> 2) * 64;    // warp row offset in tile
    const int wn = (warp & 3) * 32;     // warp col offset in tile

    const uint32_t sbase = smem_u32(sm);

    // gmem->reg assignments
    const int arow = tid >> 1;            // 0..127
    const int aseg = (tid & 1) * 16;      // 0 or 16
    const float* Abase = A + (size_t)(m0 + arow) * lda + aseg;

    // BTRANS=0: B like A. BTRANS=1: thread owns column n, half of k.
    const int bn  = tid & 127;
    const int bkh = (tid >> 7) * 16;
    const bool bok = BTRANS ? ((n0 + bn) < N) : true;
    const float* Bbase0 = B + (size_t)(n0 + arow) * ldb + aseg;   // BTRANS=0
    const float* Bbase1 = B + (size_t)bkh * ldb + n0 + bn;        // BTRANS=1 (k-major walk)

    float areg[16], breg[16];
    const int nch = K >> 5;

    // ---- gmem loads ----
    auto g2r = [&](int ci) {
        const float* ap = Abase + (ci << 5);
        #pragma unroll
        for (int j = 0; j < 4; ++j)
            *(float4*)(areg + 4*j) = *(const float4*)(ap + 4*j);
        if constexpr (!BTRANS) {
            const float* bp = Bbase0 + (ci << 5);
            #pragma unroll
            for (int j = 0; j < 4; ++j)
                *(float4*)(breg + 4*j) = *(const float4*)(bp + 4*j);
        } else {
            const float* bp = Bbase1 + (size_t)(ci << 5) * ldb;
            #pragma unroll
            for (int j = 0; j < 16; ++j)
                breg[j] = bok ? bp[(size_t)j * ldb] : 0.f;
        }
    };

    // ---- reg->smem (split bf16) ----
    auto r2s = [&](int stg) {
        char* pa_h = sm + stg * STG_BYTES;
        char* pa_l = pa_h + MAT_BYTES;
        char* pb_h = pa_h + 2*MAT_BYTES;
        char* pb_l = pa_h + 3*MAT_BYTES;
        #pragma unroll
        for (int j = 0; j < 8; ++j) {
            uint32_t h, l;
            split2(areg[2*j], areg[2*j+1], h, l);
            uint32_t off = (uint32_t)(arow * PADS + aseg + 2*j) * 2;
            *(uint32_t*)(pa_h + off) = h;
            *(uint32_t*)(pa_l + off) = l;
        }
        if constexpr (!BTRANS) {
            #pragma unroll
            for (int j = 0; j < 8; ++j) {
                uint32_t h, l;
                split2(breg[2*j], breg[2*j+1], h, l);
                uint32_t off = (uint32_t)(arow * PADS + aseg + 2*j) * 2;
                *(uint32_t*)(pb_h + off) = h;
                *(uint32_t*)(pb_l + off) = l;
            }
        } else {
            #pragma unroll
            for (int j = 0; j < 8; ++j) {
                uint32_t h, l;
                split2(breg[2*j], breg[2*j+1], h, l);
                uint32_t off = (uint32_t)(bn * PADS + bkh + 2*j) * 2;
                *(uint32_t*)(pb_h + off) = h;
                *(uint32_t*)(pb_l + off) = l;
            }
        }
    };

    float acc[4][4][4];
    #pragma unroll
    for (int i = 0; i < 4; ++i)
        #pragma unroll
        for (int j = 0; j < 4; ++j)
            #pragma unroll
            for (int q = 0; q < 4; ++q) acc[i][j][q] = 0.f;

    // ldmatrix lane addressing (element offsets within smem matrices)
    const int a_r  = wm + (lane & 15);
    const int a_c8 = (lane >> 4) << 3;
    const int b_r  = wn + (lane & 7) + ((lane >> 4) << 3);
    const int b_c8 = ((lane >> 3) & 1) << 3;

    g2r(0);
    r2s(0);

    for (int ci = 0; ci < nch; ++ci) {
        if (ci + 1 < nch) g2r(ci + 1);
        __syncthreads();

        const uint32_t st = sbase + (ci & 1) * STG_BYTES;
        const uint32_t uA_h = st;
        const uint32_t uA_l = st + MAT_BYTES;
        const uint32_t uB_h = st + 2*MAT_BYTES;
        const uint32_t uB_l = st + 3*MAT_BYTES;

        #pragma unroll
        for (int ks = 0; ks < 2; ++ks) {
            const int k0 = ks * 16;
            uint32_t ah[4][4], al[4][4], bh[2][4], bl[2][4];
            #pragma unroll
            for (int mt = 0; mt < 4; ++mt) {
                uint32_t off = (uint32_t)((a_r + mt*16) * PADS + k0 + a_c8) * 2;
                ldsm4(ah[mt], uA_h + off);
                ldsm4(al[mt], uA_l + off);
            }
            #pragma unroll
            for (int bp = 0; bp < 2; ++bp) {
                uint32_t off = (uint32_t)((b_r + bp*16) * PADS + k0 + b_c8) * 2;
                ldsm4(bh[bp], uB_h + off);
                ldsm4(bl[bp], uB_l + off);
            }
            #pragma unroll
            for (int mt = 0; mt < 4; ++mt)
                #pragma unroll
                for (int nt = 0; nt < 4; ++nt) {
                    const uint32_t* fbh = &bh[nt >> 1][(nt & 1) * 2];
                    const uint32_t* fbl = &bl[nt >> 1][(nt & 1) * 2];
                    mma16816(acc[mt][nt], ah[mt], fbh);
                    mma16816(acc[mt][nt], al[mt], fbh);
                    mma16816(acc[mt][nt], ah[mt], fbl);
                }
        }
        if (ci + 1 < nch) r2s((ci + 1) & 1);
    }

    // ---- epilogue ----
    #pragma unroll
    for (int mt = 0; mt < 4; ++mt) {
        const int r0 = m0 + wm + mt*16 + (lane >> 2);
        #pragma unroll
        for (int half = 0; half < 2; ++half) {
            const int row = r0 + half * 8;
            const size_t rb = (size_t)row * ldc;
            const size_t rx = (size_t)row * CC;
            #pragma unroll
            for (int nt = 0; nt < 4; ++nt) {
                const int col = n0 + wn + nt*8 + (lane & 3)*2;
                if (col < N) {
                    float2 o;
                    o.x = apply_epi<EPI>(acc[mt][nt][half*2+0], col,   rx, vecn, ex, exx);
                    o.y = apply_epi<EPI>(acc[mt][nt][half*2+1], col+1, rx, vecn, ex, exx);
                    *(float2*)&C[rb + col] = o;
                }
            }
        }
    }
}

// ---------------- prep: xx = shift(x)-x ; xxx = x + xx*time_maa_x ----------------
__global__ void prep_kernel(const float* __restrict__ x,
                            const float* __restrict__ tmx,
                            float* __restrict__ xx,
                            float* __restrict__ xxx)
{
    int i4 = blockIdx.x * blockDim.x + threadIdx.x;
    if (i4 >= BTC/4) return;
    size_t idx = (size_t)i4 * 4;
    int m = (int)(idx / CC);
    int c = (int)(idx % CC);
    int t = m % TT;
    float4 xv = *(const float4*)(x + idx);
    float4 xs;
    if (t == 0) { xs.x = xs.y = xs.z = xs.w = 0.f; }
    else        { xs = *(const float4*)(x + idx - CC); }
    float4 tm = *(const float4*)(tmx + c);
    float4 d, e;
    d.x = xs.x - xv.x; d.y = xs.y - xv.y; d.z = xs.z - xv.z; d.w = xs.w - xv.w;
    e.x = fmaf(d.x, tm.x, xv.x); e.y = fmaf(d.y, tm.y, xv.y);
    e.z = fmaf(d.z, tm.z, xv.z); e.w = fmaf(d.w, tm.w, xv.w);
    *(float4*)(xx  + idx) = d;
    *(float4*)(xxx + idx) = e;
}

// ---------------- WKV6 scan ----------------
__global__ void __launch_bounds__(1024)
wkv_scan(const float* __restrict__ r, const float* __restrict__ k,
         const float* __restrict__ v, const float* __restrict__ d,
         const float* __restrict__ u, float* __restrict__ y)
{
    int bh = blockIdx.x;
    int b = bh >> 4, h = bh & 15;
    int warp = threadIdx.x >> 5, lane = threadIdx.x & 31;
    size_t base = ((size_t)b * TT) * CC + h * HSZ;

    const float* rp = r + base + lane;
    const float* kp = k + base + lane;
    const float* dp = d + base + lane;
    const float* vp = v + base + warp;
    float* yp = y + ((size_t)bh * TT) * HSZ + warp;

    float uj = u[h * HSZ + lane];
    float S = 0.f;
    float rc = *rp, kc = *kp, dc = *dp, vc = *vp;

    for (int t = 0; t < TT; ++t) {
        float rn = 0.f, kn = 0.f, dn = 0.f, vn = 0.f;
        if (t + 1 < TT) {
            size_t off = (size_t)(t + 1) * CC;
            rn = rp[off]; kn = kp[off]; dn = dp[off]; vn = vp[off];
        }
        float kv  = kc * vc;
        float tmp = rc * fmaf(uj, kv, S);
        tmp += __shfl_xor_sync(0xffffffffu, tmp, 16);
        tmp += __shfl_xor_sync(0xffffffffu, tmp, 8);
        tmp += __shfl_xor_sync(0xffffffffu, tmp, 4);
        tmp += __shfl_xor_sync(0xffffffffu, tmp, 2);
        tmp += __shfl_xor_sync(0xffffffffu, tmp, 1);
        S = fmaf(dc, S, kv);
        if (lane == 0) yp[(size_t)t * HSZ] = tmp;
        rc = rn; kc = kn; dc = dn; vc = vn;
    }
}

// ---------------- per-head groupnorm + gate ----------------
__global__ void __launch_bounds__(256)
gn_gate(const float* __restrict__ y, const float* __restrict__ g,
        const float* __restrict__ lnw, const float* __restrict__ lnb,
        float* __restrict__ out)
{
    int gwid = blockIdx.x * (blockDim.x >> 5) + (threadIdx.x >> 5);
    int lane = threadIdx.x & 31;
    if (gwid >= BB * HH * TT) return;
    int bh = gwid / TT;
    int t  = gwid % TT;
    int b = bh >> 4, h = bh & 15;

    float yv = y[(size_t)gwid * HSZ + lane];
    float s = yv, s2 = yv * yv;
    #pragma unroll
    for (int off = 16; off >= 1; off >>= 1) {
        s  += __shfl_xor_sync(0xffffffffu, s,  off);
        s2 += __shfl_xor_sync(0xffffffffu, s2, off);
    }
    float mu  = s * (1.f / HSZ);
    float var = s2 * (1.f / HSZ) - mu * mu;
    float rstd = rsqrtf(var + 1e-5f);
    int cidx = h * HSZ + lane;
    float yn = fmaf((yv - mu) * rstd, lnw[cidx], lnb[cidx]);
    size_t oidx = ((size_t)b * TT + t) * CC + cidx;
    out[oidx] = yn * g[oidx];
}

// ---------------- host launcher ----------------
extern "C" void kernel_launch(void* const* d_in, const int* in_sizes, int n_in,
                              void* d_out, int out_size)
{
    const float* x     = (const float*)d_in[0];
    const float* tmxv  = (const float*)d_in[1];
    const float* tm5[5] = { (const float*)d_in[2], (const float*)d_in[3],
                            (const float*)d_in[4], (const float*)d_in[5],
                            (const float*)d_in[6] };               // w,k,v,r,g
    const float* w1    = (const float*)d_in[7];    // (C,160)
    const float* w2    = (const float*)d_in[8];    // (5,32,C)
    const float* tdec  = (const float*)d_in[9];    // (C)
    const float* tdw1  = (const float*)d_in[10];   // (C,64)
    const float* tdw2  = (const float*)d_in[11];   // (64,C)
    const float* faaaa = (const float*)d_in[12];   // (H,HS)
    const float* Wr    = (const float*)d_in[13];
    const float* Wk    = (const float*)d_in[14];
    const float* Wv    = (const float*)d_in[15];
    const float* Wg    = (const float*)d_in[16];
    const float* Wo    = (const float*)d_in[17];
    const float* lnw   = (const float*)d_in[18];
    const float* lnb   = (const float*)d_in[19];
    float* out = (float*)d_out;

    float *p_xx, *p_xxx, *p_mix, *p_x5, *p_r, *p_k, *p_v, *p_g, *p_wt, *p_dec, *p_y, *p_yg;
    cudaGetSymbolAddress((void**)&p_xx,  g_xx);
    cudaGetSymbolAddress((void**)&p_xxx, g_xxx);
    cudaGetSymbolAddress((void**)&p_mix, g_mixpre);
    cudaGetSymbolAddress((void**)&p_x5,  g_x5);
    cudaGetSymbolAddress((void**)&p_r,   g_r);
    cudaGetSymbolAddress((void**)&p_k,   g_k);
    cudaGetSymbolAddress((void**)&p_v,   g_v);
    cudaGetSymbolAddress((void**)&p_g,   g_g);
    cudaGetSymbolAddress((void**)&p_wt,  g_wt);
    cudaGetSymbolAddress((void**)&p_dec, g_dec);
    cudaGetSymbolAddress((void**)&p_y,   g_y);
    cudaGetSymbolAddress((void**)&p_yg,  g_yg);

    cudaFuncSetAttribute(mgemm<0,EPI_NONE>,  cudaFuncAttributeMaxDynamicSharedMemorySize, DSMEM_BYTES);
    cudaFuncSetAttribute(mgemm<0,EPI_SILU>,  cudaFuncAttributeMaxDynamicSharedMemorySize, DSMEM_BYTES);
    cudaFuncSetAttribute(mgemm<1,EPI_TANH>,  cudaFuncAttributeMaxDynamicSharedMemorySize, DSMEM_BYTES);
    cudaFuncSetAttribute(mgemm<1,EPI_MIX>,   cudaFuncAttributeMaxDynamicSharedMemorySize, DSMEM_BYTES);
    cudaFuncSetAttribute(mgemm<1,EPI_DECAY>, cudaFuncAttributeMaxDynamicSharedMemorySize, DSMEM_BYTES);

    // 1) token shift + xxx
    prep_kernel<<<(BTC/4 + 255)/256, 256>>>(x, tmxv, p_xx, p_xxx);

    const int GY = BT / 128;   // 128
    dim3 g512(4, GY), g160(2, GY), g64(1, GY);

    // 2) mixpre = tanh(xxx @ w1)   (BTRANS: K=512, N=160)
    mgemm<1, EPI_TANH><<<g160, 256, DSMEM_BYTES>>>(p_xxx, CC, w1, 160, p_mix, 160,
                                                   160, 512, nullptr, nullptr, nullptr);

    // 3) xf = x + xx*(tmaa_f + mixpre_f @ w2_f)   (BTRANS: K=32, N=512) x5
    for (int f = 0; f < 5; ++f) {
        mgemm<1, EPI_MIX><<<g512, 256, DSMEM_BYTES>>>(p_mix + f*32, 160,
                                                      w2 + (size_t)f*32*CC, CC,
                                                      p_x5 + (size_t)f*BTC, CC,
                                                      512, 32, tm5[f], x, p_xx);
    }

    // 4) projections (B = (N,K) row-major), K=N=512
    mgemm<0, EPI_NONE><<<g512, 256, DSMEM_BYTES>>>(p_x5 + 3*(size_t)BTC, CC, Wr, CC, p_r, CC,
                                                   512, 512, nullptr, nullptr, nullptr);
    mgemm<0, EPI_NONE><<<g512, 256, DSMEM_BYTES>>>(p_x5 + 1*(size_t)BTC, CC, Wk, CC, p_k, CC,
                                                   512, 512, nullptr, nullptr, nullptr);
    mgemm<0, EPI_NONE><<<g512, 256, DSMEM_BYTES>>>(p_x5 + 2*(size_t)BTC, CC, Wv, CC, p_v, CC,
                                                   512, 512, nullptr, nullptr, nullptr);
    mgemm<0, EPI_SILU><<<g512, 256, DSMEM_BYTES>>>(p_x5 + 4*(size_t)BTC, CC, Wg, CC, p_g, CC,
                                                   512, 512, nullptr, nullptr, nullptr);

    // 5) decay: wt = tanh(xw @ tdw1); dec = exp(-exp(tdec + wt @ tdw2))
    mgemm<1, EPI_TANH><<<g64, 256, DSMEM_BYTES>>>(p_x5 + 0, CC, tdw1, 64, p_wt, 64,
                                                  64, 512, nullptr, nullptr, nullptr);
    mgemm<1, EPI_DECAY><<<g512, 256, DSMEM_BYTES>>>(p_wt, 64, tdw2, CC, p_dec, CC,
                                                    512, 64, tdec, nullptr, nullptr);

    // 6) WKV6 scan
    wkv_scan<<<BB*HH, 1024>>>(p_r, p_k, p_v, p_dec, faaaa, p_y);

    // 7) groupnorm + gate
    gn_gate<<<(BB*HH*TT)/8, 256>>>(p_y, p_g, lnw, lnb, p_yg);

    // 8) out = yg @ Wo^T
    mgemm<0, EPI_NONE><<<g512, 256, DSMEM_BYTES>>>(p_yg, CC, Wo, CC, out, CC,
                                                   512, 512, nullptr, nullptr, nullptr);
}

// round 4
// speedup vs baseline: 1.4973x; 1.0848x over previous
#include <cuda_runtime.h>
#include <cuda_bf16.h>
#include <math.h>
#include <stdint.h>

// ---------------- problem constants ----------------
#define BB   8
#define TT   2048
#define CC   512
#define HH   16
#define HSZ  32
#define BT   (BB*TT)            // 16384
#define BTC  8388608            // BT*CC

typedef __nv_bfloat16 bf16;

// ---------------- scratch (static device memory; no allocs) ----------------
__device__ float g_xx [BTC];
__device__ float g_mixpre[BT*160];
__device__ float g_xw [BTC];
__device__ float g_r  [BTC];
__device__ float g_k  [BTC];
__device__ float g_v  [BTC];
__device__ float g_g  [BTC];
__device__ float g_wt [BT*64];
__device__ float g_dec[BTC];
__device__ float g_y  [BTC];             // layout (b,h,t,i)

// split bf16 operand buffers
__device__ bf16 g_xxx_h[BTC];
__device__ bf16 g_xxx_l[BTC];
__device__ bf16 g_xk_h[BTC]; __device__ bf16 g_xk_l[BTC];
__device__ bf16 g_xv_h[BTC]; __device__ bf16 g_xv_l[BTC];
__device__ bf16 g_xr_h[BTC]; __device__ bf16 g_xr_l[BTC];
__device__ bf16 g_xg_h[BTC]; __device__ bf16 g_xg_l[BTC];
__device__ bf16 g_yg_h[BTC]; __device__ bf16 g_yg_l[BTC];
__device__ bf16 g_w_h [5*CC*CC];   // Wr,Wk,Wv,Wg,Wo split (N,K)
__device__ bf16 g_w_l [5*CC*CC];
__device__ bf16 g_w1t_h[160*CC];   // w1 transposed (160,512)
__device__ bf16 g_w1t_l[160*CC];

// ---------------- helpers ----------------
__device__ __forceinline__ uint32_t smem_u32(const void* p) {
    uint32_t a;
    asm("{ .reg .u64 t; cvta.to.shared.u64 t, %1; cvt.u32.u64 %0, t; }" : "=r"(a) : "l"(p));
    return a;
}
__device__ __forceinline__ void ldsm4(uint32_t* r, uint32_t addr) {
    asm volatile("ldmatrix.sync.aligned.m8n8.x4.shared.b16 {%0,%1,%2,%3}, [%4];"
                 : "=r"(r[0]), "=r"(r[1]), "=r"(r[2]), "=r"(r[3]) : "r"(addr));
}
__device__ __forceinline__ void mma16816(float* c, const uint32_t* a, const uint32_t* b) {
    asm volatile("mma.sync.aligned.m16n8k16.row.col.f32.bf16.bf16.f32 "
                 "{%0,%1,%2,%3}, {%4,%5,%6,%7}, {%8,%9}, {%0,%1,%2,%3};"
                 : "+f"(c[0]), "+f"(c[1]), "+f"(c[2]), "+f"(c[3])
                 : "r"(a[0]), "r"(a[1]), "r"(a[2]), "r"(a[3]),
                   "r"(b[0]), "r"(b[1]));
}
__device__ __forceinline__ void cp16(uint32_t dst, const void* src, uint32_t sz) {
    asm volatile("cp.async.cg.shared.global [%0], [%1], 16, %2;"
                 :: "r"(dst), "l"(src), "r"(sz) : "memory");
}
#define CP_COMMIT() asm volatile("cp.async.commit_group;" ::: "memory")
#define CP_WAIT1()  asm volatile("cp.async.wait_group 1;" ::: "memory")

__device__ __forceinline__ void split2(float f0, float f1, uint32_t& hi, uint32_t& lo) {
    __nv_bfloat162 h = __floats2bfloat162_rn(f0, f1);
    float r0 = f0 - __bfloat162float(h.x);
    float r1 = f1 - __bfloat162float(h.y);
    __nv_bfloat162 l = __floats2bfloat162_rn(r0, r1);
    hi = *(uint32_t*)&h;
    lo = *(uint32_t*)&l;
}

// ---------------- epilogues ----------------
enum { EPI_NONE=0, EPI_TANH=1, EPI_SILU=2, EPI_MIX=3, EPI_DECAY=4 };

template<int EPI>
__device__ __forceinline__ float apply_epi(float v, int col, size_t rx,
                                           const float* __restrict__ vecn,
                                           const float* __restrict__ ex,
                                           const float* __restrict__ exx)
{
    if constexpr (EPI == EPI_TANH)  { return tanhf(v); }
    if constexpr (EPI == EPI_SILU)  { return v / (1.f + expf(-v)); }
    if constexpr (EPI == EPI_MIX)   { return fmaf(exx[rx+col], vecn[col] + v, ex[rx+col]); }
    if constexpr (EPI == EPI_DECAY) { return expf(-expf(vecn[col] + v)); }
    return v;
}

// ================= pgemm: split-bf16 K=512 GEMM with cp.async pipeline =================
// C[m,n] = epi( sum_k (Ah+Al)[m,k] * (Bh+Bl)[n,k] ), 3 MMA passes (AhBh, AlBh, AhBl)
// A: (BT,512) bf16 pair, B: (N,512) bf16 pair. CTA tile 128x128x32, 3-stage cp.async.
#define PPAD 40
#define PMAT (128*PPAD*2)          // 10240 B
#define PSTG (4*PMAT)              // 40960 B : Ah,Al,Bh,Bl
#define PSMEM (3*PSTG)             // 122880 B

template<int EPI>
__global__ void __launch_bounds__(256)
pgemm(const bf16* __restrict__ Ah, const bf16* __restrict__ Al,
      const bf16* __restrict__ Bh, const bf16* __restrict__ Bl,
      float* __restrict__ C, int ldc, int N,
      const float* __restrict__ vecn)
{
    extern __shared__ __align__(16) char sm[];
    const int tid  = threadIdx.x;
    const int warp = tid >> 5;
    const int lane = tid & 31;
    const int m0 = blockIdx.y * 128;
    const int n0 = blockIdx.x * 128;
    const int wm = (warp >> 2) * 64;
    const int wn = (warp & 3) * 32;
    const uint32_t sbase = smem_u32(sm);

    // cp.async issue: 2048 16B chunks/stage, 8 per thread
    auto issue = [&](int ci) {
        const uint32_t st = sbase + (uint32_t)(ci % 3) * PSTG;
        const int k0 = ci << 5;
        #pragma unroll
        for (int q = 0; q < 8; ++q) {
            const int cid  = q * 256 + tid;
            const int c    = cid & 3;
            const int r    = (cid >> 2) & 127;
            const int mat  = (cid >> 9) & 1;      // 0=hi 1=lo
            const int ab   = cid >> 10;           // 0=A 1=B
            const uint32_t dst = st + (uint32_t)ab * (2*PMAT) + (uint32_t)mat * PMAT
                               + (uint32_t)r * 80 + (uint32_t)c * 16;
            uint32_t sz = 16;
            int row;
            if (ab) {
                row = n0 + r;
                if (row >= N) { sz = 0; row = 0; }
            } else {
                row = m0 + r;
            }
            const bf16* srcb = ab ? (mat ? Bl : Bh) : (mat ? Al : Ah);
            const bf16* src  = srcb + (size_t)row * 512 + k0 + c * 8;
            cp16(dst, src, sz);
        }
        CP_COMMIT();
    };

    float acc[4][4][4];
    #pragma unroll
    for (int i = 0; i < 4; ++i)
        #pragma unroll
        for (int j = 0; j < 4; ++j)
            #pragma unroll
            for (int q = 0; q < 4; ++q) acc[i][j][q] = 0.f;

    const int a_r  = wm + (lane & 15);
    const int a_c8 = (lane >> 4) << 3;
    const int b_r  = wn + (lane & 7) + ((lane >> 4) << 3);
    const int b_c8 = ((lane >> 3) & 1) << 3;

    issue(0);
    issue(1);

    for (int ci = 0; ci < 16; ++ci) {
        CP_WAIT1();
        __syncthreads();
        if (ci + 2 < 16) issue(ci + 2);

        const uint32_t st = sbase + (uint32_t)(ci % 3) * PSTG;
        const uint32_t uA_h = st;
        const uint32_t uA_l = st + PMAT;
        const uint32_t uB_h = st + 2*PMAT;
        const uint32_t uB_l = st + 3*PMAT;

        #pragma unroll
        for (int ks = 0; ks < 2; ++ks) {
            const int k0 = ks * 16;
            uint32_t ah[4][4], al[4][4], bh[2][4], bl[2][4];
            #pragma unroll
            for (int mt = 0; mt < 4; ++mt) {
                uint32_t off = (uint32_t)((a_r + mt*16) * PPAD + k0 + a_c8) * 2;
                ldsm4(ah[mt], uA_h + off);
                ldsm4(al[mt], uA_l + off);
            }
            #pragma unroll
            for (int bp = 0; bp < 2; ++bp) {
                uint32_t off = (uint32_t)((b_r + bp*16) * PPAD + k0 + b_c8) * 2;
                ldsm4(bh[bp], uB_h + off);
                ldsm4(bl[bp], uB_l + off);
            }
            #pragma unroll
            for (int mt = 0; mt < 4; ++mt)
                #pragma unroll
                for (int nt = 0; nt < 4; ++nt) {
                    const uint32_t* fbh = &bh[nt >> 1][(nt & 1) * 2];
                    const uint32_t* fbl = &bl[nt >> 1][(nt & 1) * 2];
                    mma16816(acc[mt][nt], ah[mt], fbh);
                    mma16816(acc[mt][nt], al[mt], fbh);
                    mma16816(acc[mt][nt], ah[mt], fbl);
                }
        }
        __syncthreads();
    }

    // epilogue
    #pragma unroll
    for (int mt = 0; mt < 4; ++mt) {
        const int r0 = m0 + wm + mt*16 + (lane >> 2);
        #pragma unroll
        for (int half = 0; half < 2; ++half) {
            const int row = r0 + half * 8;
            const size_t rb = (size_t)row * ldc;
            #pragma unroll
            for (int nt = 0; nt < 4; ++nt) {
                const int col = n0 + wn + nt*8 + (lane & 3)*2;
                if (col < N) {
                    float2 o;
                    o.x = apply_epi<EPI>(acc[mt][nt][half*2+0], col,   0, vecn, nullptr, nullptr);
                    o.y = apply_epi<EPI>(acc[mt][nt][half*2+1], col+1, 0, vecn, nullptr, nullptr);
                    *(float2*)&C[rb + col] = o;
                }
            }
        }
    }
}

// ================= mgemm (round-3 GEMM, kept for the two tiny decay GEMMs) =================
#define PADS 40
#define MAT_BYTES (128*PADS*2)
#define STG_BYTES (4*MAT_BYTES)
#define DSMEM_BYTES (2*STG_BYTES)

template<int BTRANS, int EPI>
__global__ void __launch_bounds__(256)
mgemm(const float* __restrict__ A, int lda,
      const float* __restrict__ B, int ldb,
      float* __restrict__ C, int ldc,
      int N, int K,
      const float* __restrict__ vecn,
      const float* __restrict__ ex,
      const float* __restrict__ exx)
{
    extern __shared__ __align__(16) char sm[];
    const int tid  = threadIdx.x;
    const int warp = tid >> 5;
    const int lane = tid & 31;
    const int m0 = blockIdx.y * 128;
    const int n0 = blockIdx.x * 128;
    const int wm = (warp >> 2) * 64;
    const int wn = (warp & 3) * 32;

    const uint32_t sbase = smem_u32(sm);

    const int arow = tid >> 1;
    const int aseg = (tid & 1) * 16;
    const float* Abase = A + (size_t)(m0 + arow) * lda + aseg;

    const int bn  = tid & 127;
    const int bkh = (tid >> 7) * 16;
    const bool bok = BTRANS ? ((n0 + bn) < N) : true;
    const float* Bbase0 = B + (size_t)(n0 + arow) * ldb + aseg;
    const float* Bbase1 = B + (size_t)bkh * ldb + n0 + bn;

    float areg[16], breg[16];
    const int nch = K >> 5;

    auto g2r = [&](int ci) {
        const float* ap = Abase + (ci << 5);
        #pragma unroll
        for (int j = 0; j < 4; ++j)
            *(float4*)(areg + 4*j) = *(const float4*)(ap + 4*j);
        if constexpr (!BTRANS) {
            const float* bp = Bbase0 + (ci << 5);
            #pragma unroll
            for (int j = 0; j < 4; ++j)
                *(float4*)(breg + 4*j) = *(const float4*)(bp + 4*j);
        } else {
            const float* bp = Bbase1 + (size_t)(ci << 5) * ldb;
            #pragma unroll
            for (int j = 0; j < 16; ++j)
                breg[j] = bok ? bp[(size_t)j * ldb] : 0.f;
        }
    };
    auto r2s = [&](int stg) {
        char* pa_h = sm + stg * STG_BYTES;
        char* pa_l = pa_h + MAT_BYTES;
        char* pb_h = pa_h + 2*MAT_BYTES;
        char* pb_l = pa_h + 3*MAT_BYTES;
        #pragma unroll
        for (int j = 0; j < 8; ++j) {
            uint32_t h, l;
            split2(areg[2*j], areg[2*j+1], h, l);
            uint32_t off = (uint32_t)(arow * PADS + aseg + 2*j) * 2;
            *(uint32_t*)(pa_h + off) = h;
            *(uint32_t*)(pa_l + off) = l;
        }
        if constexpr (!BTRANS) {
            #pragma unroll
            for (int j = 0; j < 8; ++j) {
                uint32_t h, l;
                split2(breg[2*j], breg[2*j+1], h, l);
                uint32_t off = (uint32_t)(arow * PADS + aseg + 2*j) * 2;
                *(uint32_t*)(pb_h + off) = h;
                *(uint32_t*)(pb_l + off) = l;
            }
        } else {
            #pragma unroll
            for (int j = 0; j < 8; ++j) {
                uint32_t h, l;
                split2(breg[2*j], breg[2*j+1], h, l);
                uint32_t off = (uint32_t)(bn * PADS + bkh + 2*j) * 2;
                *(uint32_t*)(pb_h + off) = h;
                *(uint32_t*)(pb_l + off) = l;
            }
        }
    };

    float acc[4][4][4];
    #pragma unroll
    for (int i = 0; i < 4; ++i)
        #pragma unroll
        for (int j = 0; j < 4; ++j)
            #pragma unroll
            for (int q = 0; q < 4; ++q) acc[i][j][q] = 0.f;

    const int a_r  = wm + (lane & 15);
    const int a_c8 = (lane >> 4) << 3;
    const int b_r  = wn + (lane & 7) + ((lane >> 4) << 3);
    const int b_c8 = ((lane >> 3) & 1) << 3;

    g2r(0);
    r2s(0);

    for (int ci = 0; ci < nch; ++ci) {
        if (ci + 1 < nch) g2r(ci + 1);
        __syncthreads();

        const uint32_t st = sbase + (ci & 1) * STG_BYTES;
        const uint32_t uA_h = st;
        const uint32_t uA_l = st + MAT_BYTES;
        const uint32_t uB_h = st + 2*MAT_BYTES;
        const uint32_t uB_l = st + 3*MAT_BYTES;

        #pragma unroll
        for (int ks = 0; ks < 2; ++ks) {
            const int k0 = ks * 16;
            uint32_t ah[4][4], al[4][4], bh[2][4], bl[2][4];
            #pragma unroll
            for (int mt = 0; mt < 4; ++mt) {
                uint32_t off = (uint32_t)((a_r + mt*16) * PADS + k0 + a_c8) * 2;
                ldsm4(ah[mt], uA_h + off);
                ldsm4(al[mt], uA_l + off);
            }
            #pragma unroll
            for (int bp = 0; bp < 2; ++bp) {
                uint32_t off = (uint32_t)((b_r + bp*16) * PADS + k0 + b_c8) * 2;
                ldsm4(bh[bp], uB_h + off);
                ldsm4(bl[bp], uB_l + off);
            }
            #pragma unroll
            for (int mt = 0; mt < 4; ++mt)
                #pragma unroll
                for (int nt = 0; nt < 4; ++nt) {
                    const uint32_t* fbh = &bh[nt >> 1][(nt & 1) * 2];
                    const uint32_t* fbl = &bl[nt >> 1][(nt & 1) * 2];
                    mma16816(acc[mt][nt], ah[mt], fbh);
                    mma16816(acc[mt][nt], al[mt], fbh);
                    mma16816(acc[mt][nt], ah[mt], fbl);
                }
        }
        if (ci + 1 < nch) r2s((ci + 1) & 1);
    }

    #pragma unroll
    for (int mt = 0; mt < 4; ++mt) {
        const int r0 = m0 + wm + mt*16 + (lane >> 2);
        #pragma unroll
        for (int half = 0; half < 2; ++half) {
            const int row = r0 + half * 8;
            const size_t rb = (size_t)row * ldc;
            const size_t rx = (size_t)row * CC;
            #pragma unroll
            for (int nt = 0; nt < 4; ++nt) {
                const int col = n0 + wn + nt*8 + (lane & 3)*2;
                if (col < N) {
                    float2 o;
                    o.x = apply_epi<EPI>(acc[mt][nt][half*2+0], col,   rx, vecn, ex, exx);
                    o.y = apply_epi<EPI>(acc[mt][nt][half*2+1], col+1, rx, vecn, ex, exx);
                    *(float2*)&C[rb + col] = o;
                }
            }
        }
    }
}

// ---------------- weight split kernels ----------------
__global__ void split_w(const float* __restrict__ W, bf16* __restrict__ h,
                        bf16* __restrict__ l, int n)
{
    int i = blockIdx.x * blockDim.x + threadIdx.x;
    if (i >= n) return;
    float v = W[i];
    bf16 hv = __float2bfloat16(v);
    h[i] = hv;
    l[i] = __float2bfloat16(v - __bfloat162float(hv));
}
__global__ void split_w1t(const float* __restrict__ w1, bf16* __restrict__ h,
                          bf16* __restrict__ l)
{
    int i = blockIdx.x * blockDim.x + threadIdx.x;   // over 160*512
    if (i >= 160*512) return;
    int n = i >> 9, k = i & 511;
    float v = w1[(size_t)k * 160 + n];
    bf16 hv = __float2bfloat16(v);
    h[i] = hv;
    l[i] = __float2bfloat16(v - __bfloat162float(hv));
}

// ---------------- prep: xx = shift(x)-x ; xxx split bf16 ----------------
__global__ void prep_kernel(const float* __restrict__ x,
                            const float* __restrict__ tmx,
                            float* __restrict__ xx,
                            bf16* __restrict__ xxx_h,
                            bf16* __restrict__ xxx_l)
{
    int i4 = blockIdx.x * blockDim.x + threadIdx.x;
    if (i4 >= BTC/4) return;
    size_t idx = (size_t)i4 * 4;
    int m = (int)(idx / CC);
    int c = (int)(idx % CC);
    int t = m % TT;
    float4 xv = *(const float4*)(x + idx);
    float4 xs;
    if (t == 0) { xs.x = xs.y = xs.z = xs.w = 0.f; }
    else        { xs = *(const float4*)(x + idx - CC); }
    float4 tm = *(const float4*)(tmx + c);
    float4 d, e;
    d.x = xs.x - xv.x; d.y = xs.y - xv.y; d.z = xs.z - xv.z; d.w = xs.w - xv.w;
    e.x = fmaf(d.x, tm.x, xv.x); e.y = fmaf(d.y, tm.y, xv.y);
    e.z = fmaf(d.z, tm.z, xv.z); e.w = fmaf(d.w, tm.w, xv.w);
    *(float4*)(xx + idx) = d;
    uint32_t h0, h1, l0, l1;
    split2(e.x, e.y, h0, l0);
    split2(e.z, e.w, h1, l1);
    *(uint2*)(xxx_h + idx) = make_uint2(h0, h1);
    *(uint2*)(xxx_l + idx) = make_uint2(l0, l1);
}

// ---------------- mix5: fused 5-stream token-mix ----------------
// x5_f = x + xx * (time_maa_f + mixpre_f @ w2_f);  f=0 -> xw fp32, f=1..4 -> split bf16
__global__ void __launch_bounds__(256)
mix5_kernel(const float* __restrict__ mixpre,   // (BT,160)
            const float* __restrict__ w2,       // (5,32,512)
            const float* __restrict__ x,
            const float* __restrict__ xx,
            const float* __restrict__ tmw, const float* __restrict__ tmk,
            const float* __restrict__ tmv, const float* __restrict__ tmr,
            const float* __restrict__ tmg,
            float* __restrict__ xw,
            bf16* __restrict__ xk_h, bf16* __restrict__ xk_l,
            bf16* __restrict__ xv_h, bf16* __restrict__ xv_l,
            bf16* __restrict__ xr_h, bf16* __restrict__ xr_l,
            bf16* __restrict__ xg_h, bf16* __restrict__ xg_l)
{
    __shared__ float mps[32][132];
    __shared__ float w2s[32][132];
    const int tid = threadIdx.x;
    const int m0 = blockIdx.y * 128;
    const int n0 = blockIdx.x * 128;
    const int r0 = (tid >> 4) * 8;
    const int c0 = (tid & 15) * 8;
    const float* tms[5] = { tmw, tmk, tmv, tmr, tmg };
    bf16* oh[4] = { xk_h, xv_h, xr_h, xg_h };
    bf16* ol[4] = { xk_l, xv_l, xr_l, xg_l };

    const int rr  = tid >> 1, cc0 = (tid & 1) * 16;
    const int kr  = tid >> 3, cc1 = (tid & 7) * 16;

    for (int f = 0; f < 5; ++f) {
        // load mixpre slice transposed: mps[k][row]
        {
            const float* src = mixpre + (size_t)(m0 + rr) * 160 + f * 32 + cc0;
            #pragma unroll
            for (int j = 0; j < 16; j += 4) {
                float4 v4 = *(const float4*)(src + j);
                mps[cc0+j+0][rr] = v4.x; mps[cc0+j+1][rr] = v4.y;
                mps[cc0+j+2][rr] = v4.z; mps[cc0+j+3][rr] = v4.w;
            }
            const float* ws = w2 + (size_t)f * 32 * 512 + (size_t)kr * 512 + n0 + cc1;
            #pragma unroll
            for (int j = 0; j < 16; j += 4)
                *(float4*)&w2s[kr][cc1+j] = *(const float4*)(ws + j);
        }
        __syncthreads();

        float acc[8][8];
        #pragma unroll
        for (int i = 0; i < 8; ++i)
            #pragma unroll
            for (int j = 0; j < 8; ++j) acc[i][j] = 0.f;

        #pragma unroll
        for (int k = 0; k < 32; ++k) {
            float a[8], b[8];
            *(float4*)&a[0] = *(const float4*)&mps[k][r0];
            *(float4*)&a[4] = *(const float4*)&mps[k][r0+4];
            *(float4*)&b[0] = *(const float4*)&w2s[k][c0];
            *(float4*)&b[4] = *(const float4*)&w2s[k][c0+4];
            #pragma unroll
            for (int i = 0; i < 8; ++i)
                #pragma unroll
                for (int j = 0; j < 8; ++j)
                    acc[i][j] = fmaf(a[i], b[j], acc[i][j]);
        }

        float tv[8];
        #pragma unroll
        for (int j = 0; j < 8; ++j) tv[j] = __ldg(tms[f] + n0 + c0 + j);

        #pragma unroll
        for (int i = 0; i < 8; ++i) {
            const int row = m0 + r0 + i;
            const size_t base = (size_t)row * CC + n0 + c0;
            float4 x0 = *(const float4*)(x + base);
            float4 x1 = *(const float4*)(x + base + 4);
            float4 d0 = *(const float4*)(xx + base);
            float4 d1 = *(const float4*)(xx + base + 4);
            float o[8];
            o[0] = fmaf(d0.x, tv[0] + acc[i][0], x0.x);
            o[1] = fmaf(d0.y, tv[1] + acc[i][1], x0.y);
            o[2] = fmaf(d0.z, tv[2] + acc[i][2], x0.z);
            o[3] = fmaf(d0.w, tv[3] + acc[i][3], x0.w);
            o[4] = fmaf(d1.x, tv[4] + acc[i][4], x1.x);
            o[5] = fmaf(d1.y, tv[5] + acc[i][5], x1.y);
            o[6] = fmaf(d1.z, tv[6] + acc[i][6], x1.z);
            o[7] = fmaf(d1.w, tv[7] + acc[i][7], x1.w);
            if (f == 0) {
                *(float4*)(xw + base)     = make_float4(o[0], o[1], o[2], o[3]);
                *(float4*)(xw + base + 4) = make_float4(o[4], o[5], o[6], o[7]);
            } else {
                uint4 H, L;
                split2(o[0], o[1], H.x, L.x);
                split2(o[2], o[3], H.y, L.y);
                split2(o[4], o[5], H.z, L.z);
                split2(o[6], o[7], H.w, L.w);
                *(uint4*)(oh[f-1] + base) = H;
                *(uint4*)(ol[f-1] + base) = L;
            }
        }
        __syncthreads();
    }
}

// ---------------- WKV6 scan ----------------
__global__ void __launch_bounds__(1024)
wkv_scan(const float* __restrict__ r, const float* __restrict__ k,
         const float* __restrict__ v, const float* __restrict__ d,
         const float* __restrict__ u, float* __restrict__ y)
{
    int bh = blockIdx.x;
    int b = bh >> 4, h = bh & 15;
    int warp = threadIdx.x >> 5, lane = threadIdx.x & 31;
    size_t base = ((size_t)b * TT) * CC + h * HSZ;

    const float* rp = r + base + lane;
    const float* kp = k + base + lane;
    const float* dp = d + base + lane;
    const float* vp = v + base + warp;
    float* yp = y + ((size_t)bh * TT) * HSZ + warp;

    float uj = u[h * HSZ + lane];
    float S = 0.f;
    float rc = *rp, kc = *kp, dc = *dp, vc = *vp;

    for (int t = 0; t < TT; ++t) {
        float rn = 0.f, kn = 0.f, dn = 0.f, vn = 0.f;
        if (t + 1 < TT) {
            size_t off = (size_t)(t + 1) * CC;
            rn = rp[off]; kn = kp[off]; dn = dp[off]; vn = vp[off];
        }
        float kv  = kc * vc;
        float tmp = rc * fmaf(uj, kv, S);
        tmp += __shfl_xor_sync(0xffffffffu, tmp, 16);
        tmp += __shfl_xor_sync(0xffffffffu, tmp, 8);
        tmp += __shfl_xor_sync(0xffffffffu, tmp, 4);
        tmp += __shfl_xor_sync(0xffffffffu, tmp, 2);
        tmp += __shfl_xor_sync(0xffffffffu, tmp, 1);
        S = fmaf(dc, S, kv);
        if (lane == 0) yp[(size_t)t * HSZ] = tmp;
        rc = rn; kc = kn; dc = dn; vc = vn;
    }
}

// ---------------- per-head groupnorm + gate -> split bf16 ----------------
__global__ void __launch_bounds__(256)
gn_gate(const float* __restrict__ y, const float* __restrict__ g,
        const float* __restrict__ lnw, const float* __restrict__ lnb,
        bf16* __restrict__ out_h, bf16* __restrict__ out_l)
{
    int gwid = blockIdx.x * (blockDim.x >> 5) + (threadIdx.x >> 5);
    int lane = threadIdx.x & 31;
    if (gwid >= BB * HH * TT) return;
    int bh = gwid / TT;
    int t  = gwid % TT;
    int b = bh >> 4, h = bh & 15;

    float yv = y[(size_t)gwid * HSZ + lane];
    float s = yv, s2 = yv * yv;
    #pragma unroll
    for (int off = 16; off >= 1; off >>= 1) {
        s  += __shfl_xor_sync(0xffffffffu, s,  off);
        s2 += __shfl_xor_sync(0xffffffffu, s2, off);
    }
    float mu  = s * (1.f / HSZ);
    float var = s2 * (1.f / HSZ) - mu * mu;
    float rstd = rsqrtf(var + 1e-5f);
    int cidx = h * HSZ + lane;
    float yn = fmaf((yv - mu) * rstd, lnw[cidx], lnb[cidx]);
    size_t oidx = ((size_t)b * TT + t) * CC + cidx;
    float v = yn * g[oidx];
    bf16 hv = __float2bfloat16(v);
    out_h[oidx] = hv;
    out_l[oidx] = __float2bfloat16(v - __bfloat162float(hv));
}

// ---------------- host launcher ----------------
extern "C" void kernel_launch(void* const* d_in, const int* in_sizes, int n_in,
                              void* d_out, int out_size)
{
    const float* x     = (const float*)d_in[0];
    const float* tmxv  = (const float*)d_in[1];
    const float* tmw   = (const float*)d_in[2];
    const float* tmk   = (const float*)d_in[3];
    const float* tmv   = (const float*)d_in[4];
    const float* tmr   = (const float*)d_in[5];
    const float* tmg   = (const float*)d_in[6];
    const float* w1    = (const float*)d_in[7];    // (C,160)
    const float* w2    = (const float*)d_in[8];    // (5,32,C)
    const float* tdec  = (const float*)d_in[9];    // (C)
    const float* tdw1  = (const float*)d_in[10];   // (C,64)
    const float* tdw2  = (const float*)d_in[11];   // (64,C)
    const float* faaaa = (const float*)d_in[12];   // (H,HS)
    const float* Wr    = (const float*)d_in[13];
    const float* Wk    = (const float*)d_in[14];
    const float* Wv    = (const float*)d_in[15];
    const float* Wg    = (const float*)d_in[16];
    const float* Wo    = (const float*)d_in[17];
    const float* lnw   = (const float*)d_in[18];
    const float* lnb   = (const float*)d_in[19];
    float* out = (float*)d_out;

    float *p_xx, *p_mix, *p_xw, *p_r, *p_k, *p_v, *p_g, *p_wt, *p_dec, *p_y;
    bf16 *p_xxxh, *p_xxxl, *p_xkh, *p_xkl, *p_xvh, *p_xvl, *p_xrh, *p_xrl,
         *p_xgh, *p_xgl, *p_ygh, *p_ygl, *p_wh, *p_wl, *p_w1th, *p_w1tl;
    cudaGetSymbolAddress((void**)&p_xx,   g_xx);
    cudaGetSymbolAddress((void**)&p_mix,  g_mixpre);
    cudaGetSymbolAddress((void**)&p_xw,   g_xw);
    cudaGetSymbolAddress((void**)&p_r,    g_r);
    cudaGetSymbolAddress((void**)&p_k,    g_k);
    cudaGetSymbolAddress((void**)&p_v,    g_v);
    cudaGetSymbolAddress((void**)&p_g,    g_g);
    cudaGetSymbolAddress((void**)&p_wt,   g_wt);
    cudaGetSymbolAddress((void**)&p_dec,  g_dec);
    cudaGetSymbolAddress((void**)&p_y,    g_y);
    cudaGetSymbolAddress((void**)&p_xxxh, g_xxx_h);
    cudaGetSymbolAddress((void**)&p_xxxl, g_xxx_l);
    cudaGetSymbolAddress((void**)&p_xkh,  g_xk_h);
    cudaGetSymbolAddress((void**)&p_xkl,  g_xk_l);
    cudaGetSymbolAddress((void**)&p_xvh,  g_xv_h);
    cudaGetSymbolAddress((void**)&p_xvl,  g_xv_l);
    cudaGetSymbolAddress((void**)&p_xrh,  g_xr_h);
    cudaGetSymbolAddress((void**)&p_xrl,  g_xr_l);
    cudaGetSymbolAddress((void**)&p_xgh,  g_xg_h);
    cudaGetSymbolAddress((void**)&p_xgl,  g_xg_l);
    cudaGetSymbolAddress((void**)&p_ygh,  g_yg_h);
    cudaGetSymbolAddress((void**)&p_ygl,  g_yg_l);
    cudaGetSymbolAddress((void**)&p_wh,   g_w_h);
    cudaGetSymbolAddress((void**)&p_wl,   g_w_l);
    cudaGetSymbolAddress((void**)&p_w1th, g_w1t_h);
    cudaGetSymbolAddress((void**)&p_w1tl, g_w1t_l);

    cudaFuncSetAttribute(pgemm<EPI_NONE>, cudaFuncAttributeMaxDynamicSharedMemorySize, PSMEM);
    cudaFuncSetAttribute(pgemm<EPI_TANH>, cudaFuncAttributeMaxDynamicSharedMemorySize, PSMEM);
    cudaFuncSetAttribute(pgemm<EPI_SILU>, cudaFuncAttributeMaxDynamicSharedMemorySize, PSMEM);
    cudaFuncSetAttribute(mgemm<1,EPI_TANH>,  cudaFuncAttributeMaxDynamicSharedMemorySize, DSMEM_BYTES);
    cudaFuncSetAttribute(mgemm<1,EPI_DECAY>, cudaFuncAttributeMaxDynamicSharedMemorySize, DSMEM_BYTES);

    const int WN = CC*CC;   // 262144

    // 0) split weights
    split_w<<<(5*WN + 255)/256, 256>>>(Wr, p_wh, p_wl, 0);  // dummy guard; real calls below
    // NOTE: Wr..Wo are not contiguous in memory; split each separately into its slice.
    split_w<<<(WN + 255)/256, 256>>>(Wr, p_wh + 0*(size_t)WN, p_wl + 0*(size_t)WN, WN);
    split_w<<<(WN + 255)/256, 256>>>(Wk, p_wh + 1*(size_t)WN, p_wl + 1*(size_t)WN, WN);
    split_w<<<(WN + 255)/256, 256>>>(Wv, p_wh + 2*(size_t)WN, p_wl + 2*(size_t)WN, WN);
    split_w<<<(WN + 255)/256, 256>>>(Wg, p_wh + 3*(size_t)WN, p_wl + 3*(size_t)WN, WN);
    split_w<<<(WN + 255)/256, 256>>>(Wo, p_wh + 4*(size_t)WN, p_wl + 4*(size_t)WN, WN);
    split_w1t<<<(160*512 + 255)/256, 256>>>(w1, p_w1th, p_w1tl);

    // 1) token shift
    prep_kernel<<<(BTC/4 + 255)/256, 256>>>(x, tmxv, p_xx, p_xxxh, p_xxxl);

    const int GY = BT / 128;
    dim3 g512(4, GY), g160(2, GY), g64(1, GY);

    // 2) mixpre = tanh(xxx @ w1)
    pgemm<EPI_TANH><<<g160, 256, PSMEM>>>(p_xxxh, p_xxxl, p_w1th, p_w1tl,
                                          p_mix, 160, 160, nullptr);

    // 3) fused 5-stream mix
    mix5_kernel<<<g512, 256>>>(p_mix, w2, x, p_xx, tmw, tmk, tmv, tmr, tmg,
                               p_xw, p_xkh, p_xkl, p_xvh, p_xvl,
                               p_xrh, p_xrl, p_xgh, p_xgl);

    // 4) decay: wt = tanh(xw @ tdw1); dec = exp(-exp(tdec + wt @ tdw2))
    mgemm<1, EPI_TANH><<<g64, 256, DSMEM_BYTES>>>(p_xw, CC, tdw1, 64, p_wt, 64,
                                                  64, 512, nullptr, nullptr, nullptr);
    mgemm<1, EPI_DECAY><<<g512, 256, DSMEM_BYTES>>>(p_wt, 64, tdw2, CC, p_dec, CC,
                                                    512, 64, tdec, nullptr, nullptr);

    // 5) projections
    pgemm<EPI_NONE><<<g512, 256, PSMEM>>>(p_xrh, p_xrl, p_wh + 0*(size_t)WN, p_wl + 0*(size_t)WN,
                                          p_r, CC, 512, nullptr);
    pgemm<EPI_NONE><<<g512, 256, PSMEM>>>(p_xkh, p_xkl, p_wh + 1*(size_t)WN, p_wl + 1*(size_t)WN,
                                          p_k, CC, 512, nullptr);
    pgemm<EPI_NONE><<<g512, 256, PSMEM>>>(p_xvh, p_xvl, p_wh + 2*(size_t)WN, p_wl + 2*(size_t)WN,
                                          p_v, CC, 512, nullptr);
    pgemm<EPI_SILU><<<g512, 256, PSMEM>>>(p_xgh, p_xgl, p_wh + 3*(size_t)WN, p_wl + 3*(size_t)WN,
                                          p_g, CC, 512, nullptr);

    // 6) WKV6 scan
    wkv_scan<<<BB*HH, 1024>>>(p_r, p_k, p_v, p_dec, faaaa, p_y);

    // 7) groupnorm + gate -> split bf16
    gn_gate<<<(BB*HH*TT)/8, 256>>>(p_y, p_g, lnw, lnb, p_ygh, p_ygl);

    // 8) out = yg @ Wo^T
    pgemm<EPI_NONE><<<g512, 256, PSMEM>>>(p_ygh, p_ygl, p_wh + 4*(size_t)WN, p_wl + 4*(size_t)WN,
                                          out, CC, 512, nullptr);
}